// round 13
// baseline (speedup 1.0000x reference)
#include <cuda_runtime.h>
#include <cuda_fp16.h>
#include <cstdint>

#define NTOK 32768
#define DIM  1024
#define HID  512
#define NEXP 8
#define TILE_T 128
#define MAXTILES 264   // 32768/128 + 8
#define GB 256         // gate blocks
#define GT 128         // tokens per gate block

// ---------------- scratch (device globals; no allocations allowed) ----------
__device__ int   g_sel[NTOK];
__device__ int   g_blockHist[GB][8];
__device__ int   g_count[8];
__device__ int   g_perm[NTOK + NEXP * TILE_T];
__device__ float g_scorePart[(size_t)MAXTILES * 8 * 128];
__device__ float g_wtsum[MAXTILES];
__device__ float g_partial[(size_t)MAXTILES * DIM];
__device__ __half g_xh[(size_t)NTOK * DIM];
__device__ __half g_w1h[(size_t)NEXP * HID * DIM];

// ---------------- PTX helpers (all sm_80-era; no 'a' features) --------------
__device__ __forceinline__ uint32_t smem_u32(const void* p) {
    uint32_t a;
    asm("{ .reg .u64 t; cvta.to.shared.u64 t, %1; cvt.u32.u64 %0, t; }" : "=r"(a) : "l"(p));
    return a;
}
#define SW128(o) (((uint32_t)(o)) ^ ((((uint32_t)(o)) >> 3) & 0x70))

#define CPA16(dst, src) \
    asm volatile("cp.async.cg.shared.global [%0], [%1], 16;" :: "r"(dst), "l"(src))

#define LDSM4(r, addr) \
    asm volatile("ldmatrix.sync.aligned.m8n8.x4.shared.b16 {%0,%1,%2,%3}, [%4];" \
        : "=r"((r)[0]), "=r"((r)[1]), "=r"((r)[2]), "=r"((r)[3]) : "r"(addr))

#define MMA_F16(d, a, b) \
    asm volatile("mma.sync.aligned.m16n8k16.row.col.f32.f16.f16.f32 " \
        "{%0,%1,%2,%3}, {%4,%5,%6,%7}, {%8,%9}, {%0,%1,%2,%3};" \
        : "+f"((d)[0]), "+f"((d)[1]), "+f"((d)[2]), "+f"((d)[3]) \
        : "r"((a)[0]), "r"((a)[1]), "r"((a)[2]), "r"((a)[3]), \
          "r"((b)[0]), "r"((b)[1]))

// ---------------- inline tile descriptor from g_count ------------------------
struct TInfo { int e, tbase, tvalid, ntiles; };
__device__ __forceinline__ TInfo tile_info(int tile) {
    TInfo r; r.e = -1; r.tbase = 0; r.tvalid = 0;
    int idx = 0, pad = 0;
#pragma unroll
    for (int k = 0; k < 8; k++) {
        int c = g_count[k];
        int t = (c + TILE_T - 1) >> 7;
        if (r.e < 0 && tile < idx + t) {
            int li = tile - idx;
            r.e = k;
            r.tbase = pad + (li << 7);
            r.tvalid = min(TILE_T, c - (li << 7));
        }
        idx += t; pad += t << 7;
    }
    r.ntiles = idx;
    if (r.e < 0) r.e = 0;
    return r;
}

// ---------------- K1: fused gate (+x->fp16) and W1 convert/transpose --------
__global__ void __launch_bounds__(256)
k_gateCvt(const float* __restrict__ x, const float* __restrict__ gw,
          const float* __restrict__ W1) {
    if (blockIdx.x < GB) {
        __shared__ float4 sG4[NEXP * 256];   // 32 KB
        __shared__ int sHist[8];
        int tid = threadIdx.x;
        if (tid < 8) sHist[tid] = 0;
        const float4* g4 = (const float4*)gw;
#pragma unroll
        for (int i = 0; i < 8; i++) sG4[tid + i * 256] = g4[tid + i * 256];
        __syncthreads();

        int warp = tid >> 5, lane = tid & 31;
        int base = blockIdx.x * GT + warp * (GT / 8);

        for (int grp = 0; grp < 4; grp++) {
            int n0 = base + grp * 4;
            float acc[4][8];
#pragma unroll
            for (int t = 0; t < 4; t++)
#pragma unroll
                for (int e = 0; e < 8; e++) acc[t][e] = 0.f;

#pragma unroll
            for (int jh = 0; jh < 2; jh++) {
                float4 cur[4][4];
#pragma unroll
                for (int t = 0; t < 4; t++) {
                    const float4* xr4 = (const float4*)(x + (size_t)(n0 + t) * DIM);
#pragma unroll
                    for (int j = 0; j < 4; j++)
                        cur[t][j] = xr4[(jh * 4 + j) * 32 + lane];
                }
#pragma unroll
                for (int t = 0; t < 4; t++) {
                    uint2* xhr = (uint2*)(g_xh + (size_t)(n0 + t) * DIM);
#pragma unroll
                    for (int j = 0; j < 4; j++) {
                        __half2 h0 = __floats2half2_rn(cur[t][j].x, cur[t][j].y);
                        __half2 h1 = __floats2half2_rn(cur[t][j].z, cur[t][j].w);
                        xhr[(jh * 4 + j) * 32 + lane] =
                            make_uint2(*(uint32_t*)&h0, *(uint32_t*)&h1);
                    }
                }
#pragma unroll
                for (int j = 0; j < 4; j++)
#pragma unroll
                    for (int e = 0; e < 8; e++) {
                        float4 g = sG4[e * 256 + (jh * 4 + j) * 32 + lane];
#pragma unroll
                        for (int t = 0; t < 4; t++)
                            acc[t][e] += cur[t][j].x * g.x + cur[t][j].y * g.y
                                       + cur[t][j].z * g.z + cur[t][j].w * g.w;
                    }
            }
#pragma unroll
            for (int t = 0; t < 4; t++) {
#pragma unroll
                for (int e = 0; e < 8; e++)
#pragma unroll
                    for (int o = 16; o; o >>= 1)
                        acc[t][e] += __shfl_xor_sync(~0u, acc[t][e], o);
                if (lane == 0) {
                    int best = 0; float bv = acc[t][0];
#pragma unroll
                    for (int e = 1; e < 8; e++)
                        if (acc[t][e] > bv) { bv = acc[t][e]; best = e; }
                    g_sel[n0 + t] = best;
                    atomicAdd(&sHist[best], 1);
                }
            }
        }
        __syncthreads();
        if (tid < 8) g_blockHist[blockIdx.x][tid] = sHist[tid];
    } else {
        // ---- W1 convert + transpose: 4096 32x32 tiles / 128 blocks ----
        __shared__ float t[32][33];
        int bid = blockIdx.x - GB;
        int tid = threadIdx.x;
        for (int k = 0; k < 32; k++) {
            int tileId = bid * 32 + k;
            int e  = tileId >> 9;
            int rem = tileId & 511;
            int db = rem >> 4, hb = rem & 15;
            const float* src = W1 + ((size_t)e * DIM + db * 32) * HID + hb * 32;
            {
                int row = tid >> 3, c4 = (tid & 7) * 4;
                float4 v = *(const float4*)(src + (size_t)row * HID + c4);
                t[row][c4] = v.x; t[row][c4 + 1] = v.y;
                t[row][c4 + 2] = v.z; t[row][c4 + 3] = v.w;
            }
            __syncthreads();
            {
                int dp = (tid & 15) * 2, hh = tid >> 4;
#pragma unroll
                for (int j = 0; j < 2; j++) {
                    int h = hh + j * 16;
                    __half2 hv = __floats2half2_rn(t[dp][h], t[dp + 1][h]);
                    size_t o = ((size_t)e * HID + hb * 32 + h) * DIM + db * 32 + dp;
                    *(__half2*)(g_w1h + o) = hv;
                }
            }
            __syncthreads();
        }
    }
}

// ---------------- K3: scatter with per-block local scan ----------------------
__global__ void __launch_bounds__(256)
k_scatter() {
    __shared__ int sSel[GT];
    __shared__ int sCnt[8], sPre[8], sOffE[8];
    int tid = threadIdx.x, warp = tid >> 5, lane = tid & 31;
    int b = blockIdx.x;

    if (tid < GT) sSel[tid] = g_sel[b * GT + tid];

    {
        int tot = 0, pre = 0;
#pragma unroll
        for (int j = 0; j < 8; j++) {
            int bb = lane + j * 32;
            int h = g_blockHist[bb][warp];
            tot += h;
            pre += (bb < b) ? h : 0;
        }
#pragma unroll
        for (int o = 16; o; o >>= 1) {
            tot += __shfl_xor_sync(~0u, tot, o);
            pre += __shfl_xor_sync(~0u, pre, o);
        }
        if (lane == 0) { sCnt[warp] = tot; sPre[warp] = pre; }
    }
    __syncthreads();
    if (tid == 0) {
        int pad = 0;
#pragma unroll
        for (int e = 0; e < 8; e++) {
            sOffE[e] = pad + sPre[e];
            if (b == 0) g_count[e] = sCnt[e];
            pad += ((sCnt[e] + TILE_T - 1) >> 7) << 7;
        }
    }
    __syncthreads();
    if (tid < GT) {
        int e = sSel[tid];
        int rank = 0;
        for (int i = 0; i < tid; i++) rank += (sSel[i] == e);
        g_perm[sOffE[e] + rank] = b * GT + tid;
    }
}

// ---------------- K4: score GEMM 128Mx64N, 3 CTAs/SM, 3-stage pipeline -------
#define KC 64
#define SMX 0          // 3 stages x 16KB (X: 128 x 64 fp16)
#define SMW 49152      // 3 stages x 8KB  (W: 64 x 64 fp16)
#define SMB1 73728
#define SMW2 73984
#define SMRED 74240
#define SMTOK 75264
#define SMTOT 75776

__device__ __forceinline__ void load_chunk(uint32_t smb, const int* sTok,
                                           const char* xB, const char* wB,
                                           int d0, int stage, int tid) {
#pragma unroll
    for (int it = 0; it < 4; it++) {   // X: 128 rows x 8 c16
        int seg = it * 256 + tid;
        int row = seg >> 3, c16 = seg & 7;
        uint32_t doff = SW128((uint32_t)(row * 128 + c16 * 16));
        size_t xsrc = (size_t)sTok[row] * (DIM * 2) + d0 * 2 + c16 * 16;
        CPA16(smb + SMX + stage * 16384 + doff, xB + xsrc);
    }
#pragma unroll
    for (int it = 0; it < 2; it++) {   // W: 64 rows x 8 c16
        int seg = it * 256 + tid;
        int row = seg >> 3, c16 = seg & 7;
        uint32_t doff = SW128((uint32_t)(row * 128 + c16 * 16));
        size_t wsrc = (size_t)row * (DIM * 2) + d0 * 2 + c16 * 16;
        CPA16(smb + SMW + stage * 8192 + doff, wB + wsrc);
    }
    asm volatile("cp.async.commit_group;" ::: "memory");
}

__global__ void __launch_bounds__(256, 3)
k_score(const float* __restrict__ b1, const float* __restrict__ w2) {
    int tile = blockIdx.x;
    TInfo ti = tile_info(tile);
    if (tile >= ti.ntiles) return;
    int nc = blockIdx.y;   // 0..7, 64 h-cols each
    int e = ti.e, tbase = ti.tbase, tvalid = ti.tvalid;

    extern __shared__ char sm[];
    uint32_t smb = smem_u32(sm);
    int tid = threadIdx.x, wid = tid >> 5, lane = tid & 31;

    int*   sTok = (int*)(sm + SMTOK);
    float* b1s  = (float*)(sm + SMB1);
    float* w2s  = (float*)(sm + SMW2);
    float* sRed = (float*)(sm + SMRED);

    if (tid < 128)
        sTok[tid] = g_perm[tbase + min(tid, tvalid - 1)];
    if (tid < 64) {
        int h = nc * 64 + tid;
        b1s[tid] = b1[e * HID + h];
        w2s[tid] = w2[e * HID + h];
    }
    __syncthreads();

    const char* xB = (const char*)g_xh;
    const char* wB = (const char*)(g_w1h + ((size_t)e * HID + (size_t)nc * 64) * DIM);

    int wm = wid >> 1, wn = wid & 1;
    int m0 = wm * 32, n0 = wn * 32;

    uint32_t aBase  = (uint32_t)((m0 + (lane & 15)) * 128 + (lane >> 4) * 16);
    uint32_t bBase4 = (uint32_t)((n0 + (lane >> 4) * 8 + (lane & 7)) * 128 +
                                 ((lane >> 3) & 1) * 16);

    float acc[2][4][4];
#pragma unroll
    for (int mt = 0; mt < 2; mt++)
#pragma unroll
        for (int nt = 0; nt < 4; nt++)
#pragma unroll
            for (int j = 0; j < 4; j++) acc[mt][nt][j] = 0.f;

    load_chunk(smb, sTok, xB, wB, 0, 0, tid);
    load_chunk(smb, sTok, xB, wB, KC, 1, tid);

    for (int i = 0; i < 16; i++) {
        if (i < 15) {
            asm volatile("cp.async.wait_group 1;" ::: "memory");
        } else {
            asm volatile("cp.async.wait_group 0;" ::: "memory");
        }
        __syncthreads();
        if (i + 2 < 16)
            load_chunk(smb, sTok, xB, wB, (i + 2) * KC, (i + 2) % 3, tid);

        uint32_t xs = smb + SMX + (i % 3) * 16384;
        uint32_t ws = smb + SMW + (i % 3) * 8192;
#pragma unroll
        for (int kk = 0; kk < 4; kk++) {
            uint32_t a[2][4];
#pragma unroll
            for (int mt = 0; mt < 2; mt++)
                LDSM4(a[mt], xs + SW128(aBase + mt * 2048 + kk * 32));
#pragma unroll
            for (int nt2 = 0; nt2 < 2; nt2++) {
                uint32_t b4[4];
                LDSM4(b4, ws + SW128(bBase4 + nt2 * 2048 + kk * 32));
#pragma unroll
                for (int mt = 0; mt < 2; mt++) {
                    MMA_F16(acc[mt][nt2 * 2],     a[mt], b4);
                    MMA_F16(acc[mt][nt2 * 2 + 1], a[mt], b4 + 2);
                }
            }
        }
    }

    // epilogue: +b1, tanh, dot w2 over this CTA's 64 h-cols
    int g = lane >> 2, qc = lane & 3;
    float rs[4] = {0.f, 0.f, 0.f, 0.f};
#pragma unroll
    for (int mt = 0; mt < 2; mt++)
#pragma unroll
        for (int nt = 0; nt < 4; nt++) {
            int hl = wn * 32 + nt * 8 + qc * 2;
            float w20 = w2s[hl], w21 = w2s[hl + 1];
            float bb0 = b1s[hl], bb1 = b1s[hl + 1];
            rs[mt * 2 + 0] += tanhf(acc[mt][nt][0] + bb0) * w20
                            + tanhf(acc[mt][nt][1] + bb1) * w21;
            rs[mt * 2 + 1] += tanhf(acc[mt][nt][2] + bb0) * w20
                            + tanhf(acc[mt][nt][3] + bb1) * w21;
        }
#pragma unroll
    for (int j = 0; j < 4; j++) {
        rs[j] += __shfl_xor_sync(~0u, rs[j], 1);
        rs[j] += __shfl_xor_sync(~0u, rs[j], 2);
    }
    __syncthreads();
    if (qc == 0) {
        sRed[wn * 128 + m0 + g]      = rs[0];
        sRed[wn * 128 + m0 + g + 8]  = rs[1];
        sRed[wn * 128 + m0 + g + 16] = rs[2];
        sRed[wn * 128 + m0 + g + 24] = rs[3];
    }
    __syncthreads();
    if (tid < 128)
        g_scorePart[((size_t)tile * 8 + nc) * 128 + tid] = sRed[tid] + sRed[128 + tid];
}

// ---------------- K6: pooled partials, softmax-free (raw exp weights) --------
__global__ void __launch_bounds__(128, 8)
k_poolA(const float* __restrict__ b2) {
    int tile = blockIdx.x;
    TInfo ti = tile_info(tile);
    if (tile >= ti.ntiles) return;
    int e = ti.e, tbase = ti.tbase, tvalid = ti.tvalid;
    __shared__ float sWt[TILE_T];
    __shared__ int   sN[TILE_T];
    __shared__ float sSum[4];
    int tid = threadIdx.x;  // 128
    {
        float wt = 0.f;
        if (tid < tvalid) {
            size_t tb = ((size_t)tile * 8) * 128 + tid;
            float s = b2[e];
#pragma unroll
            for (int j = 0; j < 8; j++) s += g_scorePart[tb + j * 128];
            wt = expf(s);      // |s| small; no max-subtraction needed
            sN[tid] = g_perm[tbase + tid];
        } else sN[tid] = 0;
        sWt[tid] = wt;
        if (blockIdx.y == 0) {
            float v = wt;
#pragma unroll
            for (int o = 16; o; o >>= 1) v += __shfl_xor_sync(~0u, v, o);
            if ((tid & 31) == 0) sSum[tid >> 5] = v;
        }
    }
    __syncthreads();
    if (blockIdx.y == 0 && tid == 0)
        g_wtsum[tile] = (sSum[0] + sSum[1]) + (sSum[2] + sSum[3]);

    int dh = blockIdx.y * 128 + tid;  // half2 index
    float2 a0 = make_float2(0.f, 0.f), a1 = a0, a2 = a0, a3 = a0;
#pragma unroll 2
    for (int t = 0; t < TILE_T; t += 4) {
        float2 f0 = __half22float2(((const __half2*)(g_xh + (size_t)sN[t]     * DIM))[dh]);
        float2 f1 = __half22float2(((const __half2*)(g_xh + (size_t)sN[t + 1] * DIM))[dh]);
        float2 f2 = __half22float2(((const __half2*)(g_xh + (size_t)sN[t + 2] * DIM))[dh]);
        float2 f3 = __half22float2(((const __half2*)(g_xh + (size_t)sN[t + 3] * DIM))[dh]);
        a0.x = fmaf(sWt[t],     f0.x, a0.x); a0.y = fmaf(sWt[t],     f0.y, a0.y);
        a1.x = fmaf(sWt[t + 1], f1.x, a1.x); a1.y = fmaf(sWt[t + 1], f1.y, a1.y);
        a2.x = fmaf(sWt[t + 2], f2.x, a2.x); a2.y = fmaf(sWt[t + 2], f2.y, a2.y);
        a3.x = fmaf(sWt[t + 3], f3.x, a3.x); a3.y = fmaf(sWt[t + 3], f3.y, a3.y);
    }
    float2 acc = make_float2((a0.x + a1.x) + (a2.x + a3.x),
                             (a0.y + a1.y) + (a2.y + a3.y));
    ((float2*)g_partial)[(size_t)tile * (DIM / 2) + dh] = acc;
}

// ---------------- K7: fixed-order reduce + normalize -> output ---------------
__global__ void k_poolB(float* __restrict__ out) {
    int e = blockIdx.x;
    int d = threadIdx.x;  // 1024
    int t0 = 0, t1 = 0, idx = 0;
#pragma unroll
    for (int k = 0; k < 8; k++) {
        int t = (g_count[k] + TILE_T - 1) >> 7;
        if (k == e) { t0 = idx; t1 = idx + t; }
        idx += t;
    }
    float acc = 0.f, wsum = 0.f;
    for (int t = t0; t < t1; t++) {
        acc  += g_partial[(size_t)t * DIM + d];
        wsum += g_wtsum[t];
    }
    out[e * DIM + d] = (wsum > 0.f) ? acc / wsum : 0.f;
}

// ---------------- entry ------------------------------------------------------
extern "C" void kernel_launch(void* const* d_in, const int* in_sizes, int n_in,
                              void* d_out, int out_size) {
    const float* x   = (const float*)d_in[0];
    const float* gw  = (const float*)d_in[1];
    const float* W1  = (const float*)d_in[2];
    const float* b1  = (const float*)d_in[3];
    const float* w2  = (const float*)d_in[4];
    const float* b2  = (const float*)d_in[5];
    float* out = (float*)d_out;

    cudaFuncSetAttribute(k_score, cudaFuncAttributeMaxDynamicSharedMemorySize, SMTOT);

    k_gateCvt<<<GB + 128, 256>>>(x, gw, W1);
    k_scatter<<<GB, 256>>>();
    k_score<<<dim3(MAXTILES, 8), 256, SMTOT>>>(b1, w2);
    k_poolA<<<dim3(MAXTILES, 4), 128>>>(b2);
    k_poolB<<<8, 1024>>>(out);
}

// round 14
// speedup vs baseline: 1.0411x; 1.0411x over previous
#include <cuda_runtime.h>
#include <cuda_fp16.h>
#include <cstdint>

#define NTOK 32768
#define DIM  1024
#define HID  512
#define NEXP 8
#define TILE_T 128
#define MAXTILES 264   // 32768/128 + 8
#define GB 256         // gate blocks
#define GT 128         // tokens per gate block

// ---------------- scratch (device globals; no allocations allowed) ----------
__device__ int   g_sel[NTOK];
__device__ int   g_blockHist[GB][8];
__device__ int   g_count[8];
__device__ int   g_perm[NTOK + NEXP * TILE_T];
__device__ float g_scorePart[(size_t)MAXTILES * 4 * 128];
__device__ float g_wtsum[MAXTILES];
__device__ float g_partial[(size_t)MAXTILES * 2 * DIM];
__device__ __half g_xh[(size_t)NTOK * DIM];
__device__ __half g_w1h[(size_t)NEXP * HID * DIM];

// ---------------- PTX helpers (all sm_80-era; no 'a' features) --------------
__device__ __forceinline__ uint32_t smem_u32(const void* p) {
    uint32_t a;
    asm("{ .reg .u64 t; cvta.to.shared.u64 t, %1; cvt.u32.u64 %0, t; }" : "=r"(a) : "l"(p));
    return a;
}
#define SW128(o) (((uint32_t)(o)) ^ ((((uint32_t)(o)) >> 3) & 0x70))

#define CPA16(dst, src) \
    asm volatile("cp.async.cg.shared.global [%0], [%1], 16;" :: "r"(dst), "l"(src))

#define LDSM4(r, addr) \
    asm volatile("ldmatrix.sync.aligned.m8n8.x4.shared.b16 {%0,%1,%2,%3}, [%4];" \
        : "=r"((r)[0]), "=r"((r)[1]), "=r"((r)[2]), "=r"((r)[3]) : "r"(addr))

#define MMA_F16(d, a, b) \
    asm volatile("mma.sync.aligned.m16n8k16.row.col.f32.f16.f16.f32 " \
        "{%0,%1,%2,%3}, {%4,%5,%6,%7}, {%8,%9}, {%0,%1,%2,%3};" \
        : "+f"((d)[0]), "+f"((d)[1]), "+f"((d)[2]), "+f"((d)[3]) \
        : "r"((a)[0]), "r"((a)[1]), "r"((a)[2]), "r"((a)[3]), \
          "r"((b)[0]), "r"((b)[1]))

// ---------------- inline tile descriptor from g_count ------------------------
struct TInfo { int e, tbase, tvalid, ntiles; };
__device__ __forceinline__ TInfo tile_info(int tile) {
    TInfo r; r.e = -1; r.tbase = 0; r.tvalid = 0;
    int idx = 0, pad = 0;
#pragma unroll
    for (int k = 0; k < 8; k++) {
        int c = g_count[k];
        int t = (c + TILE_T - 1) >> 7;
        if (r.e < 0 && tile < idx + t) {
            int li = tile - idx;
            r.e = k;
            r.tbase = pad + (li << 7);
            r.tvalid = min(TILE_T, c - (li << 7));
        }
        idx += t; pad += t << 7;
    }
    r.ntiles = idx;
    if (r.e < 0) r.e = 0;
    return r;
}

// ---------------- K1: fused gate (+x->fp16) and W1 convert/transpose --------
__global__ void __launch_bounds__(256)
k_gateCvt(const float* __restrict__ x, const float* __restrict__ gw,
          const float* __restrict__ W1) {
    if (blockIdx.x < GB) {
        __shared__ float4 sG4[NEXP * 256];   // 32 KB
        __shared__ int sHist[8];
        int tid = threadIdx.x;
        if (tid < 8) sHist[tid] = 0;
        const float4* g4 = (const float4*)gw;
#pragma unroll
        for (int i = 0; i < 8; i++) sG4[tid + i * 256] = g4[tid + i * 256];
        __syncthreads();

        int warp = tid >> 5, lane = tid & 31;
        int base = blockIdx.x * GT + warp * (GT / 8);

        for (int grp = 0; grp < 4; grp++) {
            int n0 = base + grp * 4;
            float acc[4][8];
#pragma unroll
            for (int t = 0; t < 4; t++)
#pragma unroll
                for (int e = 0; e < 8; e++) acc[t][e] = 0.f;

#pragma unroll
            for (int jh = 0; jh < 2; jh++) {
                float4 cur[4][4];
#pragma unroll
                for (int t = 0; t < 4; t++) {
                    const float4* xr4 = (const float4*)(x + (size_t)(n0 + t) * DIM);
#pragma unroll
                    for (int j = 0; j < 4; j++)
                        cur[t][j] = xr4[(jh * 4 + j) * 32 + lane];
                }
#pragma unroll
                for (int t = 0; t < 4; t++) {
                    uint2* xhr = (uint2*)(g_xh + (size_t)(n0 + t) * DIM);
#pragma unroll
                    for (int j = 0; j < 4; j++) {
                        __half2 h0 = __floats2half2_rn(cur[t][j].x, cur[t][j].y);
                        __half2 h1 = __floats2half2_rn(cur[t][j].z, cur[t][j].w);
                        xhr[(jh * 4 + j) * 32 + lane] =
                            make_uint2(*(uint32_t*)&h0, *(uint32_t*)&h1);
                    }
                }
#pragma unroll
                for (int j = 0; j < 4; j++)
#pragma unroll
                    for (int e = 0; e < 8; e++) {
                        float4 g = sG4[e * 256 + (jh * 4 + j) * 32 + lane];
#pragma unroll
                        for (int t = 0; t < 4; t++)
                            acc[t][e] += cur[t][j].x * g.x + cur[t][j].y * g.y
                                       + cur[t][j].z * g.z + cur[t][j].w * g.w;
                    }
            }
#pragma unroll
            for (int t = 0; t < 4; t++) {
#pragma unroll
                for (int e = 0; e < 8; e++)
#pragma unroll
                    for (int o = 16; o; o >>= 1)
                        acc[t][e] += __shfl_xor_sync(~0u, acc[t][e], o);
                if (lane == 0) {
                    int best = 0; float bv = acc[t][0];
#pragma unroll
                    for (int e = 1; e < 8; e++)
                        if (acc[t][e] > bv) { bv = acc[t][e]; best = e; }
                    g_sel[n0 + t] = best;
                    atomicAdd(&sHist[best], 1);
                }
            }
        }
        __syncthreads();
        if (tid < 8) g_blockHist[blockIdx.x][tid] = sHist[tid];
    } else {
        // ---- W1 convert + transpose: 4096 32x32 tiles / 128 blocks ----
        __shared__ float t[32][33];
        int bid = blockIdx.x - GB;
        int tid = threadIdx.x;
        for (int k = 0; k < 32; k++) {
            int tileId = bid * 32 + k;
            int e  = tileId >> 9;
            int rem = tileId & 511;
            int db = rem >> 4, hb = rem & 15;
            const float* src = W1 + ((size_t)e * DIM + db * 32) * HID + hb * 32;
            {
                int row = tid >> 3, c4 = (tid & 7) * 4;
                float4 v = *(const float4*)(src + (size_t)row * HID + c4);
                t[row][c4] = v.x; t[row][c4 + 1] = v.y;
                t[row][c4 + 2] = v.z; t[row][c4 + 3] = v.w;
            }
            __syncthreads();
            {
                int dp = (tid & 15) * 2, hh = tid >> 4;
#pragma unroll
                for (int j = 0; j < 2; j++) {
                    int h = hh + j * 16;
                    __half2 hv = __floats2half2_rn(t[dp][h], t[dp + 1][h]);
                    size_t o = ((size_t)e * HID + hb * 32 + h) * DIM + db * 32 + dp;
                    *(__half2*)(g_w1h + o) = hv;
                }
            }
            __syncthreads();
        }
    }
}

// ---------------- K3: scatter, ballot-based ranks ----------------------------
__global__ void __launch_bounds__(256)
k_scatter() {
    __shared__ int sCnt[8], sPre[8], sOffE[8];
    __shared__ int sWCnt[4][8];   // per-warp per-expert counts (4 token-warps)
    int tid = threadIdx.x, warp = tid >> 5, lane = tid & 31;
    int b = blockIdx.x;

    // phase 1: warp e computes expert-e totals + prefix over blocks < b
    {
        int tot = 0, pre = 0;
#pragma unroll
        for (int j = 0; j < 8; j++) {
            int bb = lane + j * 32;
            int h = g_blockHist[bb][warp];
            tot += h;
            pre += (bb < b) ? h : 0;
        }
#pragma unroll
        for (int o = 16; o; o >>= 1) {
            tot += __shfl_xor_sync(~0u, tot, o);
            pre += __shfl_xor_sync(~0u, pre, o);
        }
        if (lane == 0) { sCnt[warp] = tot; sPre[warp] = pre; }
    }
    // phase 2: warps 0-3 do ballot ranks for the 128 tokens
    int e = -1, rankw = 0;
    if (warp < 4) {
        e = g_sel[b * GT + tid];
        uint32_t below = (1u << lane) - 1u;
#pragma unroll
        for (int k = 0; k < 8; k++) {
            uint32_t m = __ballot_sync(~0u, e == k);
            if (e == k) rankw = __popc(m & below);
            if (lane == 0) sWCnt[warp][k] = __popc(m);
        }
    }
    __syncthreads();
    if (tid == 0) {
        int pad = 0;
#pragma unroll
        for (int k = 0; k < 8; k++) {
            sOffE[k] = pad + sPre[k];
            if (b == 0) g_count[k] = sCnt[k];
            pad += ((sCnt[k] + TILE_T - 1) >> 7) << 7;
        }
    }
    __syncthreads();
    if (warp < 4) {
        int off = 0;
#pragma unroll
        for (int w = 0; w < 4; w++)
            if (w < warp) off += sWCnt[w][e];
        g_perm[sOffE[e] + off + rankw] = b * GT + tid;
    }
}

// ---------------- K4: score GEMM on HMMA (round-12 config) ------------------
#define KC 64
#define SMX 0         // 3 stages x 16KB
#define SMW 49152     // 3 stages x 16KB
#define SMB1 98304
#define SMW2 98816
#define SMRED 99328
#define SMTOK 100352
#define SMTOT 100864

__device__ __forceinline__ void load_chunk(uint32_t smb, const int* sTok,
                                           const char* xB, const char* wB,
                                           int d0, int stage, int tid) {
#pragma unroll
    for (int it = 0; it < 4; it++) {
        int seg = it * 256 + tid;           // 0..1023
        int row = seg >> 3, c16 = seg & 7;  // 16B column block
        uint32_t doff = SW128((uint32_t)(row * 128 + c16 * 16));
        size_t xsrc = (size_t)sTok[row] * (DIM * 2) + d0 * 2 + c16 * 16;
        CPA16(smb + SMX + stage * 16384 + doff, xB + xsrc);
        size_t wsrc = (size_t)row * (DIM * 2) + d0 * 2 + c16 * 16;
        CPA16(smb + SMW + stage * 16384 + doff, wB + wsrc);
    }
    asm volatile("cp.async.commit_group;" ::: "memory");
}

__global__ void __launch_bounds__(256, 2)
k_score(const float* __restrict__ b1, const float* __restrict__ w2) {
    int tile = blockIdx.x;
    TInfo ti = tile_info(tile);
    if (tile >= ti.ntiles) return;
    int nc = blockIdx.y;
    int e = ti.e, tbase = ti.tbase, tvalid = ti.tvalid;

    extern __shared__ char sm[];
    uint32_t smb = smem_u32(sm);
    int tid = threadIdx.x, wid = tid >> 5, lane = tid & 31;

    int*   sTok = (int*)(sm + SMTOK);
    float* b1s  = (float*)(sm + SMB1);
    float* w2s  = (float*)(sm + SMW2);
    float* sRed = (float*)(sm + SMRED);

    if (tid < 128) {
        sTok[tid] = g_perm[tbase + min(tid, tvalid - 1)];
        int h = nc * 128 + tid;
        b1s[tid] = b1[e * HID + h];
        w2s[tid] = w2[e * HID + h];
    }
    __syncthreads();

    const char* xB = (const char*)g_xh;
    const char* wB = (const char*)(g_w1h + ((size_t)e * HID + (size_t)nc * 128) * DIM);

    int wm = wid >> 1, wn = wid & 1;
    int m0 = wm * 32, n0 = wn * 64;

    uint32_t aBase  = (uint32_t)((m0 + (lane & 15)) * 128 + (lane >> 4) * 16);
    uint32_t bBase4 = (uint32_t)((n0 + (lane >> 4) * 8 + (lane & 7)) * 128 +
                                 ((lane >> 3) & 1) * 16);

    float acc[2][8][4];
#pragma unroll
    for (int mt = 0; mt < 2; mt++)
#pragma unroll
        for (int nt = 0; nt < 8; nt++)
#pragma unroll
            for (int j = 0; j < 4; j++) acc[mt][nt][j] = 0.f;

    load_chunk(smb, sTok, xB, wB, 0, 0, tid);
    load_chunk(smb, sTok, xB, wB, KC, 1, tid);

    for (int i = 0; i < 16; i++) {
        if (i < 15) {
            asm volatile("cp.async.wait_group 1;" ::: "memory");
        } else {
            asm volatile("cp.async.wait_group 0;" ::: "memory");
        }
        __syncthreads();
        if (i + 2 < 16)
            load_chunk(smb, sTok, xB, wB, (i + 2) * KC, (i + 2) % 3, tid);

        uint32_t xs = smb + SMX + (i % 3) * 16384;
        uint32_t ws = smb + SMW + (i % 3) * 16384;
#pragma unroll
        for (int kk = 0; kk < 4; kk++) {
            uint32_t a[2][4];
#pragma unroll
            for (int mt = 0; mt < 2; mt++)
                LDSM4(a[mt], xs + SW128(aBase + mt * 2048 + kk * 32));
#pragma unroll
            for (int nt2 = 0; nt2 < 4; nt2++) {
                uint32_t b4[4];
                LDSM4(b4, ws + SW128(bBase4 + nt2 * 2048 + kk * 32));
#pragma unroll
                for (int mt = 0; mt < 2; mt++) {
                    MMA_F16(acc[mt][nt2 * 2],     a[mt], b4);
                    MMA_F16(acc[mt][nt2 * 2 + 1], a[mt], b4 + 2);
                }
            }
        }
    }

    // epilogue: +b1, tanh, dot w2 over this CTA's 128 h-cols
    int g = lane >> 2, qc = lane & 3;
    float rs[4] = {0.f, 0.f, 0.f, 0.f};
#pragma unroll
    for (int mt = 0; mt < 2; mt++)
#pragma unroll
        for (int nt = 0; nt < 8; nt++) {
            int hl = wn * 64 + nt * 8 + qc * 2;
            float w20 = w2s[hl], w21 = w2s[hl + 1];
            float bb0 = b1s[hl], bb1 = b1s[hl + 1];
            rs[mt * 2 + 0] += tanhf(acc[mt][nt][0] + bb0) * w20
                            + tanhf(acc[mt][nt][1] + bb1) * w21;
            rs[mt * 2 + 1] += tanhf(acc[mt][nt][2] + bb0) * w20
                            + tanhf(acc[mt][nt][3] + bb1) * w21;
        }
#pragma unroll
    for (int j = 0; j < 4; j++) {
        rs[j] += __shfl_xor_sync(~0u, rs[j], 1);
        rs[j] += __shfl_xor_sync(~0u, rs[j], 2);
    }
    __syncthreads();
    if (qc == 0) {
        sRed[wn * 128 + m0 + g]      = rs[0];
        sRed[wn * 128 + m0 + g + 8]  = rs[1];
        sRed[wn * 128 + m0 + g + 16] = rs[2];
        sRed[wn * 128 + m0 + g + 24] = rs[3];
    }
    __syncthreads();
    if (tid < 128)
        g_scorePart[((size_t)tile * 4 + nc) * 128 + tid] = sRed[tid] + sRed[128 + tid];
}

// ---------------- K6: pooled partials, z-split for occupancy -----------------
__global__ void __launch_bounds__(128, 8)
k_poolA(const float* __restrict__ b2) {
    int tile = blockIdx.x;
    TInfo ti = tile_info(tile);
    if (tile >= ti.ntiles) return;
    int e = ti.e, tbase = ti.tbase, tvalid = ti.tvalid;
    int z = blockIdx.z;
    __shared__ float sWt[TILE_T];
    __shared__ int   sN[TILE_T];
    __shared__ float sSum[4];
    int tid = threadIdx.x;  // 128
    {
        float wt = 0.f;
        if (tid < tvalid) {
            size_t tb = ((size_t)tile * 4) * 128 + tid;
            float s = b2[e] + g_scorePart[tb] + g_scorePart[tb + 128]
                    + g_scorePart[tb + 256] + g_scorePart[tb + 384];
            wt = expf(s);      // |s| small; no max-subtraction needed
            sN[tid] = g_perm[tbase + tid];
        } else sN[tid] = 0;
        sWt[tid] = wt;
        if (blockIdx.y == 0 && z == 0) {
            float v = wt;
#pragma unroll
            for (int o = 16; o; o >>= 1) v += __shfl_xor_sync(~0u, v, o);
            if ((tid & 31) == 0) sSum[tid >> 5] = v;
        }
    }
    __syncthreads();
    if (blockIdx.y == 0 && z == 0 && tid == 0)
        g_wtsum[tile] = (sSum[0] + sSum[1]) + (sSum[2] + sSum[3]);

    int dh = blockIdx.y * 128 + tid;  // half2 index
    int tb0 = z * 64;
    float2 a0 = make_float2(0.f, 0.f), a1 = a0, a2 = a0, a3 = a0;
#pragma unroll 2
    for (int t = tb0; t < tb0 + 64; t += 4) {
        float2 f0 = __half22float2(((const __half2*)(g_xh + (size_t)sN[t]     * DIM))[dh]);
        float2 f1 = __half22float2(((const __half2*)(g_xh + (size_t)sN[t + 1] * DIM))[dh]);
        float2 f2 = __half22float2(((const __half2*)(g_xh + (size_t)sN[t + 2] * DIM))[dh]);
        float2 f3 = __half22float2(((const __half2*)(g_xh + (size_t)sN[t + 3] * DIM))[dh]);
        a0.x = fmaf(sWt[t],     f0.x, a0.x); a0.y = fmaf(sWt[t],     f0.y, a0.y);
        a1.x = fmaf(sWt[t + 1], f1.x, a1.x); a1.y = fmaf(sWt[t + 1], f1.y, a1.y);
        a2.x = fmaf(sWt[t + 2], f2.x, a2.x); a2.y = fmaf(sWt[t + 2], f2.y, a2.y);
        a3.x = fmaf(sWt[t + 3], f3.x, a3.x); a3.y = fmaf(sWt[t + 3], f3.y, a3.y);
    }
    float2 acc = make_float2((a0.x + a1.x) + (a2.x + a3.x),
                             (a0.y + a1.y) + (a2.y + a3.y));
    ((float2*)g_partial)[((size_t)tile * 2 + z) * (DIM / 2) + dh] = acc;
}

// ---------------- K7: fixed-order reduce + normalize -> output ---------------
__global__ void k_poolB(float* __restrict__ out) {
    int e = blockIdx.x;
    int d = threadIdx.x;  // 1024
    int t0 = 0, t1 = 0, idx = 0;
#pragma unroll
    for (int k = 0; k < 8; k++) {
        int t = (g_count[k] + TILE_T - 1) >> 7;
        if (k == e) { t0 = idx; t1 = idx + t; }
        idx += t;
    }
    float acc = 0.f, wsum = 0.f;
    for (int t = t0; t < t1; t++) {
        acc += g_partial[((size_t)t * 2) * DIM + d]
             + g_partial[((size_t)t * 2 + 1) * DIM + d];
        wsum += g_wtsum[t];
    }
    out[e * DIM + d] = (wsum > 0.f) ? acc / wsum : 0.f;
}

// ---------------- entry ------------------------------------------------------
extern "C" void kernel_launch(void* const* d_in, const int* in_sizes, int n_in,
                              void* d_out, int out_size) {
    const float* x   = (const float*)d_in[0];
    const float* gw  = (const float*)d_in[1];
    const float* W1  = (const float*)d_in[2];
    const float* b1  = (const float*)d_in[3];
    const float* w2  = (const float*)d_in[4];
    const float* b2  = (const float*)d_in[5];
    float* out = (float*)d_out;

    cudaFuncSetAttribute(k_score, cudaFuncAttributeMaxDynamicSharedMemorySize, SMTOT);

    k_gateCvt<<<GB + 128, 256>>>(x, gw, W1);
    k_scatter<<<GB, 256>>>();
    k_score<<<dim3(MAXTILES, 4), 256, SMTOT>>>(b1, w2);
    dim3 gA(MAXTILES, 4, 2);
    k_poolA<<<gA, 128>>>(b2);
    k_poolB<<<8, 1024>>>(out);
}

// round 15
// speedup vs baseline: 1.0511x; 1.0097x over previous
#include <cuda_runtime.h>
#include <cuda_fp16.h>
#include <cstdint>

#define NTOK 32768
#define DIM  1024
#define HID  512
#define NEXP 8
#define TILE_T 128
#define MAXTILES 264   // 32768/128 + 8
#define GB 256         // gate blocks
#define GT 128         // tokens per gate block

// ---------------- scratch (device globals; no allocations allowed) ----------
__device__ int   g_sel[NTOK];
__device__ int   g_blockHist[GB][8];
__device__ int   g_count[8];
__device__ int   g_perm[NTOK + NEXP * TILE_T];
__device__ float g_scorePart[(size_t)MAXTILES * 4 * 128];
__device__ float g_wtsum[MAXTILES];
__device__ float g_partial[(size_t)MAXTILES * 4 * DIM];
__device__ __half g_xh[(size_t)NTOK * DIM];
__device__ __half g_w1h[(size_t)NEXP * HID * DIM];

// ---------------- PTX helpers (all sm_80-era; no 'a' features) --------------
__device__ __forceinline__ uint32_t smem_u32(const void* p) {
    uint32_t a;
    asm("{ .reg .u64 t; cvta.to.shared.u64 t, %1; cvt.u32.u64 %0, t; }" : "=r"(a) : "l"(p));
    return a;
}
#define SW128(o) (((uint32_t)(o)) ^ ((((uint32_t)(o)) >> 3) & 0x70))

#define CPA16(dst, src) \
    asm volatile("cp.async.cg.shared.global [%0], [%1], 16;" :: "r"(dst), "l"(src))

#define LDSM4(r, addr) \
    asm volatile("ldmatrix.sync.aligned.m8n8.x4.shared.b16 {%0,%1,%2,%3}, [%4];" \
        : "=r"((r)[0]), "=r"((r)[1]), "=r"((r)[2]), "=r"((r)[3]) : "r"(addr))

#define MMA_F16(d, a, b) \
    asm volatile("mma.sync.aligned.m16n8k16.row.col.f32.f16.f16.f32 " \
        "{%0,%1,%2,%3}, {%4,%5,%6,%7}, {%8,%9}, {%0,%1,%2,%3};" \
        : "+f"((d)[0]), "+f"((d)[1]), "+f"((d)[2]), "+f"((d)[3]) \
        : "r"((a)[0]), "r"((a)[1]), "r"((a)[2]), "r"((a)[3]), \
          "r"((b)[0]), "r"((b)[1]))

// ---------------- inline tile descriptor from g_count ------------------------
struct TInfo { int e, tbase, tvalid, ntiles; };
__device__ __forceinline__ TInfo tile_info(int tile) {
    TInfo r; r.e = -1; r.tbase = 0; r.tvalid = 0;
    int idx = 0, pad = 0;
#pragma unroll
    for (int k = 0; k < 8; k++) {
        int c = g_count[k];
        int t = (c + TILE_T - 1) >> 7;
        if (r.e < 0 && tile < idx + t) {
            int li = tile - idx;
            r.e = k;
            r.tbase = pad + (li << 7);
            r.tvalid = min(TILE_T, c - (li << 7));
        }
        idx += t; pad += t << 7;
    }
    r.ntiles = idx;
    if (r.e < 0) r.e = 0;
    return r;
}

// ---------------- K1: fused gate (+x->fp16) and W1 convert/transpose --------
__global__ void __launch_bounds__(256)
k_gateCvt(const float* __restrict__ x, const float* __restrict__ gw,
          const float* __restrict__ W1) {
    if (blockIdx.x < GB) {
        __shared__ float4 sG4[NEXP * 256];   // 32 KB
        __shared__ int sHist[8];
        int tid = threadIdx.x;
        if (tid < 8) sHist[tid] = 0;
        const float4* g4 = (const float4*)gw;
#pragma unroll
        for (int i = 0; i < 8; i++) sG4[tid + i * 256] = g4[tid + i * 256];
        __syncthreads();

        int warp = tid >> 5, lane = tid & 31;
        int base = blockIdx.x * GT + warp * (GT / 8);

        for (int grp = 0; grp < 4; grp++) {
            int n0 = base + grp * 4;
            float acc[4][8];
#pragma unroll
            for (int t = 0; t < 4; t++)
#pragma unroll
                for (int e = 0; e < 8; e++) acc[t][e] = 0.f;

#pragma unroll
            for (int jh = 0; jh < 2; jh++) {
                float4 cur[4][4];
#pragma unroll
                for (int t = 0; t < 4; t++) {
                    const float4* xr4 = (const float4*)(x + (size_t)(n0 + t) * DIM);
#pragma unroll
                    for (int j = 0; j < 4; j++)
                        cur[t][j] = xr4[(jh * 4 + j) * 32 + lane];
                }
#pragma unroll
                for (int t = 0; t < 4; t++) {
                    uint2* xhr = (uint2*)(g_xh + (size_t)(n0 + t) * DIM);
#pragma unroll
                    for (int j = 0; j < 4; j++) {
                        __half2 h0 = __floats2half2_rn(cur[t][j].x, cur[t][j].y);
                        __half2 h1 = __floats2half2_rn(cur[t][j].z, cur[t][j].w);
                        xhr[(jh * 4 + j) * 32 + lane] =
                            make_uint2(*(uint32_t*)&h0, *(uint32_t*)&h1);
                    }
                }
#pragma unroll
                for (int j = 0; j < 4; j++)
#pragma unroll
                    for (int e = 0; e < 8; e++) {
                        float4 g = sG4[e * 256 + (jh * 4 + j) * 32 + lane];
#pragma unroll
                        for (int t = 0; t < 4; t++)
                            acc[t][e] += cur[t][j].x * g.x + cur[t][j].y * g.y
                                       + cur[t][j].z * g.z + cur[t][j].w * g.w;
                    }
            }
#pragma unroll
            for (int t = 0; t < 4; t++) {
#pragma unroll
                for (int e = 0; e < 8; e++)
#pragma unroll
                    for (int o = 16; o; o >>= 1)
                        acc[t][e] += __shfl_xor_sync(~0u, acc[t][e], o);
                if (lane == 0) {
                    int best = 0; float bv = acc[t][0];
#pragma unroll
                    for (int e = 1; e < 8; e++)
                        if (acc[t][e] > bv) { bv = acc[t][e]; best = e; }
                    g_sel[n0 + t] = best;
                    atomicAdd(&sHist[best], 1);
                }
            }
        }
        __syncthreads();
        if (tid < 8) g_blockHist[blockIdx.x][tid] = sHist[tid];
    } else {
        // ---- W1 convert + transpose: 4096 32x32 tiles / 256 blocks ----
        __shared__ float t[32][33];
        int bid = blockIdx.x - GB;
        int tid = threadIdx.x;
        for (int k = 0; k < 16; k++) {
            int tileId = bid * 16 + k;
            int e  = tileId >> 9;
            int rem = tileId & 511;
            int db = rem >> 4, hb = rem & 15;
            const float* src = W1 + ((size_t)e * DIM + db * 32) * HID + hb * 32;
            {
                int row = tid >> 3, c4 = (tid & 7) * 4;
                float4 v = *(const float4*)(src + (size_t)row * HID + c4);
                t[row][c4] = v.x; t[row][c4 + 1] = v.y;
                t[row][c4 + 2] = v.z; t[row][c4 + 3] = v.w;
            }
            __syncthreads();
            {
                int dp = (tid & 15) * 2, hh = tid >> 4;
#pragma unroll
                for (int j = 0; j < 2; j++) {
                    int h = hh + j * 16;
                    __half2 hv = __floats2half2_rn(t[dp][h], t[dp + 1][h]);
                    size_t o = ((size_t)e * HID + hb * 32 + h) * DIM + db * 32 + dp;
                    *(__half2*)(g_w1h + o) = hv;
                }
            }
            __syncthreads();
        }
    }
}

// ---------------- K3: scatter, ballot-based ranks ----------------------------
__global__ void __launch_bounds__(256)
k_scatter() {
    __shared__ int sCnt[8], sPre[8], sOffE[8];
    __shared__ int sWCnt[4][8];
    int tid = threadIdx.x, warp = tid >> 5, lane = tid & 31;
    int b = blockIdx.x;

    {
        int tot = 0, pre = 0;
#pragma unroll
        for (int j = 0; j < 8; j++) {
            int bb = lane + j * 32;
            int h = g_blockHist[bb][warp];
            tot += h;
            pre += (bb < b) ? h : 0;
        }
#pragma unroll
        for (int o = 16; o; o >>= 1) {
            tot += __shfl_xor_sync(~0u, tot, o);
            pre += __shfl_xor_sync(~0u, pre, o);
        }
        if (lane == 0) { sCnt[warp] = tot; sPre[warp] = pre; }
    }
    int e = -1, rankw = 0;
    if (warp < 4) {
        e = g_sel[b * GT + tid];
        uint32_t below = (1u << lane) - 1u;
#pragma unroll
        for (int k = 0; k < 8; k++) {
            uint32_t m = __ballot_sync(~0u, e == k);
            if (e == k) rankw = __popc(m & below);
            if (lane == 0) sWCnt[warp][k] = __popc(m);
        }
    }
    __syncthreads();
    if (tid == 0) {
        int pad = 0;
#pragma unroll
        for (int k = 0; k < 8; k++) {
            sOffE[k] = pad + sPre[k];
            if (b == 0) g_count[k] = sCnt[k];
            pad += ((sCnt[k] + TILE_T - 1) >> 7) << 7;
        }
    }
    __syncthreads();
    if (warp < 4) {
        int off = 0;
#pragma unroll
        for (int w = 0; w < 4; w++)
            if (w < warp) off += sWCnt[w][e];
        g_perm[sOffE[e] + off + rankw] = b * GT + tid;
    }
}

// ---------------- K4: score GEMM on HMMA (round-12 config) ------------------
#define KC 64
#define SMX 0         // 3 stages x 16KB
#define SMW 49152     // 3 stages x 16KB
#define SMB1 98304
#define SMW2 98816
#define SMRED 99328
#define SMTOK 100352
#define SMTOT 100864

__device__ __forceinline__ void load_chunk(uint32_t smb, const int* sTok,
                                           const char* xB, const char* wB,
                                           int d0, int stage, int tid) {
#pragma unroll
    for (int it = 0; it < 4; it++) {
        int seg = it * 256 + tid;           // 0..1023
        int row = seg >> 3, c16 = seg & 7;  // 16B column block
        uint32_t doff = SW128((uint32_t)(row * 128 + c16 * 16));
        size_t xsrc = (size_t)sTok[row] * (DIM * 2) + d0 * 2 + c16 * 16;
        CPA16(smb + SMX + stage * 16384 + doff, xB + xsrc);
        size_t wsrc = (size_t)row * (DIM * 2) + d0 * 2 + c16 * 16;
        CPA16(smb + SMW + stage * 16384 + doff, wB + wsrc);
    }
    asm volatile("cp.async.commit_group;" ::: "memory");
}

__global__ void __launch_bounds__(256, 2)
k_score(const float* __restrict__ b1, const float* __restrict__ w2) {
    int tile = blockIdx.x;
    TInfo ti = tile_info(tile);
    if (tile >= ti.ntiles) return;
    int nc = blockIdx.y;
    int e = ti.e, tbase = ti.tbase, tvalid = ti.tvalid;

    extern __shared__ char sm[];
    uint32_t smb = smem_u32(sm);
    int tid = threadIdx.x, wid = tid >> 5, lane = tid & 31;

    int*   sTok = (int*)(sm + SMTOK);
    float* b1s  = (float*)(sm + SMB1);
    float* w2s  = (float*)(sm + SMW2);
    float* sRed = (float*)(sm + SMRED);

    if (tid < 128) {
        sTok[tid] = g_perm[tbase + min(tid, tvalid - 1)];
        int h = nc * 128 + tid;
        b1s[tid] = b1[e * HID + h];
        w2s[tid] = w2[e * HID + h];
    }
    __syncthreads();

    const char* xB = (const char*)g_xh;
    const char* wB = (const char*)(g_w1h + ((size_t)e * HID + (size_t)nc * 128) * DIM);

    int wm = wid >> 1, wn = wid & 1;
    int m0 = wm * 32, n0 = wn * 64;

    uint32_t aBase  = (uint32_t)((m0 + (lane & 15)) * 128 + (lane >> 4) * 16);
    uint32_t bBase4 = (uint32_t)((n0 + (lane >> 4) * 8 + (lane & 7)) * 128 +
                                 ((lane >> 3) & 1) * 16);

    float acc[2][8][4];
#pragma unroll
    for (int mt = 0; mt < 2; mt++)
#pragma unroll
        for (int nt = 0; nt < 8; nt++)
#pragma unroll
            for (int j = 0; j < 4; j++) acc[mt][nt][j] = 0.f;

    load_chunk(smb, sTok, xB, wB, 0, 0, tid);
    load_chunk(smb, sTok, xB, wB, KC, 1, tid);

    for (int i = 0; i < 16; i++) {
        if (i < 15) {
            asm volatile("cp.async.wait_group 1;" ::: "memory");
        } else {
            asm volatile("cp.async.wait_group 0;" ::: "memory");
        }
        __syncthreads();
        if (i + 2 < 16)
            load_chunk(smb, sTok, xB, wB, (i + 2) * KC, (i + 2) % 3, tid);

        uint32_t xs = smb + SMX + (i % 3) * 16384;
        uint32_t ws = smb + SMW + (i % 3) * 16384;
#pragma unroll
        for (int kk = 0; kk < 4; kk++) {
            uint32_t a[2][4];
#pragma unroll
            for (int mt = 0; mt < 2; mt++)
                LDSM4(a[mt], xs + SW128(aBase + mt * 2048 + kk * 32));
#pragma unroll
            for (int nt2 = 0; nt2 < 4; nt2++) {
                uint32_t b4[4];
                LDSM4(b4, ws + SW128(bBase4 + nt2 * 2048 + kk * 32));
#pragma unroll
                for (int mt = 0; mt < 2; mt++) {
                    MMA_F16(acc[mt][nt2 * 2],     a[mt], b4);
                    MMA_F16(acc[mt][nt2 * 2 + 1], a[mt], b4 + 2);
                }
            }
        }
    }

    // epilogue: +b1, tanh, dot w2 over this CTA's 128 h-cols
    int g = lane >> 2, qc = lane & 3;
    float rs[4] = {0.f, 0.f, 0.f, 0.f};
#pragma unroll
    for (int mt = 0; mt < 2; mt++)
#pragma unroll
        for (int nt = 0; nt < 8; nt++) {
            int hl = wn * 64 + nt * 8 + qc * 2;
            float w20 = w2s[hl], w21 = w2s[hl + 1];
            float bb0 = b1s[hl], bb1 = b1s[hl + 1];
            rs[mt * 2 + 0] += tanhf(acc[mt][nt][0] + bb0) * w20
                            + tanhf(acc[mt][nt][1] + bb1) * w21;
            rs[mt * 2 + 1] += tanhf(acc[mt][nt][2] + bb0) * w20
                            + tanhf(acc[mt][nt][3] + bb1) * w21;
        }
#pragma unroll
    for (int j = 0; j < 4; j++) {
        rs[j] += __shfl_xor_sync(~0u, rs[j], 1);
        rs[j] += __shfl_xor_sync(~0u, rs[j], 2);
    }
    __syncthreads();
    if (qc == 0) {
        sRed[wn * 128 + m0 + g]      = rs[0];
        sRed[wn * 128 + m0 + g + 8]  = rs[1];
        sRed[wn * 128 + m0 + g + 16] = rs[2];
        sRed[wn * 128 + m0 + g + 24] = rs[3];
    }
    __syncthreads();
    if (tid < 128)
        g_scorePart[((size_t)tile * 4 + nc) * 128 + tid] = sRed[tid] + sRed[128 + tid];
}

// ---------------- K6: pooled partials, vectorized gather ---------------------
// block: 128 threads cover full DIM (8 halves each); blockIdx.y = token quarter
__global__ void __launch_bounds__(128, 8)
k_poolA(const float* __restrict__ b2) {
    int tile = blockIdx.x;
    TInfo ti = tile_info(tile);
    if (tile >= ti.ntiles) return;
    int e = ti.e, tbase = ti.tbase, tvalid = ti.tvalid;
    int z = blockIdx.y;   // 0..3, 32 tokens each
    __shared__ float sWt[TILE_T];
    __shared__ int   sN[TILE_T];
    __shared__ float sSum[4];
    int tid = threadIdx.x;  // 128
    {
        float wt = 0.f;
        if (tid < tvalid) {
            size_t tb = ((size_t)tile * 4) * 128 + tid;
            float s = b2[e] + g_scorePart[tb] + g_scorePart[tb + 128]
                    + g_scorePart[tb + 256] + g_scorePart[tb + 384];
            wt = expf(s);      // |s| small; no max-subtraction needed
            sN[tid] = g_perm[tbase + tid];
        } else sN[tid] = 0;
        sWt[tid] = wt;
        if (z == 0) {
            float v = wt;
#pragma unroll
            for (int o = 16; o; o >>= 1) v += __shfl_xor_sync(~0u, v, o);
            if ((tid & 31) == 0) sSum[tid >> 5] = v;
        }
    }
    __syncthreads();
    if (z == 0 && tid == 0)
        g_wtsum[tile] = (sSum[0] + sSum[1]) + (sSum[2] + sSum[3]);

    // 8 halves per thread; 32 tokens; unroll 2 for MLP
    float acc[8];
#pragma unroll
    for (int j = 0; j < 8; j++) acc[j] = 0.f;
    int tb0 = z * 32;
#pragma unroll 2
    for (int t = tb0; t < tb0 + 32; t++) {
        uint4 v = ((const uint4*)(g_xh + (size_t)sN[t] * DIM))[tid];
        float w = sWt[t];
        float2 f0 = __half22float2(*(__half2*)&v.x);
        float2 f1 = __half22float2(*(__half2*)&v.y);
        float2 f2 = __half22float2(*(__half2*)&v.z);
        float2 f3 = __half22float2(*(__half2*)&v.w);
        acc[0] = fmaf(w, f0.x, acc[0]); acc[1] = fmaf(w, f0.y, acc[1]);
        acc[2] = fmaf(w, f1.x, acc[2]); acc[3] = fmaf(w, f1.y, acc[3]);
        acc[4] = fmaf(w, f2.x, acc[4]); acc[5] = fmaf(w, f2.y, acc[5]);
        acc[6] = fmaf(w, f3.x, acc[6]); acc[7] = fmaf(w, f3.y, acc[7]);
    }
    float4* out4 = (float4*)(g_partial + ((size_t)tile * 4 + z) * DIM + tid * 8);
    out4[0] = make_float4(acc[0], acc[1], acc[2], acc[3]);
    out4[1] = make_float4(acc[4], acc[5], acc[6], acc[7]);
}

// ---------------- K7: fixed-order reduce + normalize -> output ---------------
__global__ void k_poolB(float* __restrict__ out) {
    int e = blockIdx.x;
    int d = threadIdx.x;  // 1024
    int t0 = 0, t1 = 0, idx = 0;
#pragma unroll
    for (int k = 0; k < 8; k++) {
        int t = (g_count[k] + TILE_T - 1) >> 7;
        if (k == e) { t0 = idx; t1 = idx + t; }
        idx += t;
    }
    float acc = 0.f, wsum = 0.f;
    for (int t = t0; t < t1; t++) {
        acc += (g_partial[((size_t)t * 4 + 0) * DIM + d]
              + g_partial[((size_t)t * 4 + 1) * DIM + d])
             + (g_partial[((size_t)t * 4 + 2) * DIM + d]
              + g_partial[((size_t)t * 4 + 3) * DIM + d]);
        wsum += g_wtsum[t];
    }
    out[e * DIM + d] = (wsum > 0.f) ? acc / wsum : 0.f;
}

// ---------------- entry ------------------------------------------------------
extern "C" void kernel_launch(void* const* d_in, const int* in_sizes, int n_in,
                              void* d_out, int out_size) {
    const float* x   = (const float*)d_in[0];
    const float* gw  = (const float*)d_in[1];
    const float* W1  = (const float*)d_in[2];
    const float* b1  = (const float*)d_in[3];
    const float* w2  = (const float*)d_in[4];
    const float* b2  = (const float*)d_in[5];
    float* out = (float*)d_out;

    cudaFuncSetAttribute(k_score, cudaFuncAttributeMaxDynamicSharedMemorySize, SMTOT);

    k_gateCvt<<<GB + 256, 256>>>(x, gw, W1);
    k_scatter<<<GB, 256>>>();
    k_score<<<dim3(MAXTILES, 4), 256, SMTOT>>>(b1, w2);
    k_poolA<<<dim3(MAXTILES, 4), 128>>>(b2);
    k_poolB<<<8, 1024>>>(out);
}